// round 15
// baseline (speedup 1.0000x reference)
#include <cuda_runtime.h>
#include <cuda_bf16.h>
#include <math.h>
#include <stdint.h>

#define IMG 192
#define HWC (192*192)
#define NWSIDE 24
#define NWPB 576
#define NWTOT 1152
typedef __nv_bfloat16 bf16;

// ---------------- scratch (device globals) ----------------
static __device__ bf16  g_wbf [262144];
static __device__ bf16  g_a512[(size_t)2*512*HWC];
static __device__ bf16  g_g256[(size_t)2*256*HWC];
static __device__ bf16  g_qkv [(size_t)2*384*HWC];
static __device__ bf16  g_ao  [(size_t)2*128*HWC];
static __device__ bf16  g_x1n [(size_t)2*128*HWC];
static __device__ bf16  g_x2n [(size_t)2*128*HWC];
static __device__ float g_x1  [(size_t)2*128*HWC];
static __device__ float g_x2  [(size_t)2*128*HWC];

// Fast erf-GELU (A&S 7.1.26, |err|<1.5e-7)
__device__ __forceinline__ float gelu_erf(float v) {
    float z  = fabsf(v) * 0.70710678118654752f;
    float t  = __fdividef(1.0f, fmaf(0.3275911f, z, 1.0f));
    float p  = fmaf(t, 1.061405429f, -1.453152027f);
    p = fmaf(t, p, 1.421413741f);
    p = fmaf(t, p, -0.284496736f);
    p = fmaf(t, p, 0.254829592f);
    float e  = p * t * __expf(-z * z);
    float er = 1.0f - e;
    er = copysignf(er, v);
    return 0.5f * v * (1.0f + er);
}
__device__ __forceinline__ uint32_t smem_u32(const void* p) {
    uint32_t a;
    asm("{ .reg .u64 t; cvta.to.shared.u64 t, %1; cvt.u32.u64 %0, t; }" : "=r"(a) : "l"(p));
    return a;
}
__device__ __forceinline__ void cpa16(void* dst, const void* src) {
    uint32_t d = smem_u32(dst);
    asm volatile("cp.async.cg.shared.global [%0], [%1], 16;" :: "r"(d), "l"(src) : "memory");
}
#define CP_COMMIT() asm volatile("cp.async.commit_group;" ::: "memory")
#define CP_WAIT(n)  asm volatile("cp.async.wait_group %0;" :: "n"(n) : "memory")

__device__ __forceinline__ void ldsm4(uint32_t* r, uint32_t addr) {
    asm volatile("ldmatrix.sync.aligned.m8n8.x4.shared.b16 {%0,%1,%2,%3}, [%4];"
        : "=r"(r[0]), "=r"(r[1]), "=r"(r[2]), "=r"(r[3]) : "r"(addr));
}
__device__ __forceinline__ void ldsm4t(uint32_t* r, uint32_t addr) {
    asm volatile("ldmatrix.sync.aligned.m8n8.x4.trans.shared.b16 {%0,%1,%2,%3}, [%4];"
        : "=r"(r[0]), "=r"(r[1]), "=r"(r[2]), "=r"(r[3]) : "r"(addr));
}
__device__ __forceinline__ void mma16(float* c, const uint32_t* a, const uint32_t* b) {
    asm volatile("mma.sync.aligned.m16n8k16.row.col.f32.bf16.bf16.f32 "
        "{%0,%1,%2,%3}, {%4,%5,%6,%7}, {%8,%9}, {%0,%1,%2,%3};"
        : "+f"(c[0]), "+f"(c[1]), "+f"(c[2]), "+f"(c[3])
        : "r"(a[0]), "r"(a[1]), "r"(a[2]), "r"(a[3]), "r"(b[0]), "r"(b[1]));
}

// smem byte offsets — N=64px tiles, 2 CTAs/SM
#define SH  136
#define SBH 72
#define OFF_A0   0
#define OFF_A1   34816        // also fp32 RMSIN staging [128][68]
#define OFF_B0   69632
#define OFF_B1   88064
#define OFF_BIAS 106496
#define OFF_RS   108544
#define OFF_RB   109056
#define OFF_RBUF 109568
#define SMB      110592

// =====================================================================
// bf16 mma GEMM (unchanged from round 14: NPX weight reuse)
// =====================================================================
template<int KT, int MT, int MODE, bool RMSOUT, bool RMSIN, int NPX>
__global__ void __launch_bounds__(256, 2)
tc_gemm(const bf16* __restrict__ in, const bf16* __restrict__ W,
        const float* __restrict__ bias,
        const float* __restrict__ res, const float* __restrict__ scale_ptr,
        float* __restrict__ out, bf16* __restrict__ outb,
        bf16* __restrict__ outn,
        const float* __restrict__ rs2, const float* __restrict__ rb2,
        const float* __restrict__ inf)
{
    constexpr int NSUB  = (MODE == 1) ? 2 : 1;
    constexpr int NS    = KT * MT * NSUB;
    constexpr int KTOT  = KT * 128;
    constexpr int OCOUT = (MODE == 1) ? 256 : MT * 128;
    constexpr int NBIAS = (MODE == 1) ? 512 : MT * 128;
    constexpr int NACC  = (MODE == 1) ? 2 : 1;
    constexpr int SLOTS = NACC * NPX;

    extern __shared__ char sm[];
    float* bs   = (float*)(sm + OFF_BIAS);
    float* rsv  = (float*)(sm + OFF_RS);
    float* rbv  = (float*)(sm + OFF_RB);
    float* rbuf = (float*)(sm + OFF_RBUF);
    const uint32_t smb = smem_u32(sm);

    const int tid = threadIdx.x, lane = tid & 31, wid = tid >> 5;
    const int wm = wid & 3, wn = wid >> 2;
    const int gp = blockIdx.x * (64 * NPX);
    const int b  = gp / HWC;
    const int p0 = gp - b * HWC;
    const bf16* inb = RMSIN ? nullptr : (in + (size_t)b * KTOT * HWC + p0);

    for (int i = tid; i < NBIAS; i += 256) bs[i] = bias[i];
    if (RMSOUT) for (int i = tid; i < 128; i += 256) { rsv[i] = rs2[i]; rbv[i] = rb2[i]; }

    const int a_m = (lane & 7) + ((lane >> 3) & 1) * 8;
    const int a_k = (lane >> 4) * 8;
    const int b_k = (lane & 7) + ((lane >> 3) & 1) * 8;
    const int b_n = wn * 32 + (lane >> 4) * 8;

    float acc[SLOTS][2][4][4];

    if (RMSIN) {
        float* stg = (float*)(sm + OFF_A1);
        #pragma unroll
        for (int h = 0; h < NPX; ++h) {
            const float* xf = inf + (size_t)b * 128 * HWC + p0 + h * 64;
            for (int i = tid; i < 2048; i += 256) {
                int c = i >> 4, p4 = (i & 15) * 4;
                cpa16(stg + c * 68 + p4, xf + (size_t)c * HWC + p4);
            }
            CP_COMMIT();
            if (h == NPX - 1) {
                const bf16* wt = W;
                for (int i = tid; i < 2048; i += 256) {
                    int o = i >> 4, k8 = (i & 15) * 8;
                    cpa16(sm + OFF_A0 + (o * SH + k8) * 2, wt + (size_t)o * KTOT + k8);
                }
                CP_COMMIT();
                CP_WAIT(1);
            } else {
                CP_WAIT(0);
            }
            __syncthreads();
            int px = tid & 63, part = tid >> 6;
            float ss = 0.f;
            #pragma unroll 8
            for (int c = part * 32; c < part * 32 + 32; ++c) {
                float v = stg[c * 68 + px]; ss += v * v;
            }
            rbuf[part * 64 + px] = ss;
            __syncthreads();
            if (tid < 64)
                rbuf[tid] = rsqrtf((rbuf[tid] + rbuf[64 + tid] + rbuf[128 + tid]
                                  + rbuf[192 + tid]) * (1.0f / 128.0f) + 1e-6f);
            __syncthreads();
            bf16* Bh = (bf16*)(sm + (h ? OFF_B1 : OFF_B0));
            for (int i = tid; i < 4096; i += 256) {
                int c = i >> 5, p2 = (i & 31) * 2;
                float sc = rs2[c], bb = rb2[c];
                float v0 = sc * stg[c * 68 + p2]     * rbuf[p2]     + bb;
                float v1 = sc * stg[c * 68 + p2 + 1] * rbuf[p2 + 1] + bb;
                *(__nv_bfloat162*)&Bh[c * SBH + p2] =
                    __halves2bfloat162(__float2bfloat16(v0), __float2bfloat16(v1));
            }
            __syncthreads();
        }
    } else {
        if (KT == 1) {
            #pragma unroll
            for (int h = 0; h < NPX; ++h) {
                char* bd = sm + (h ? OFF_B1 : OFF_B0);
                for (int i = tid; i < 1024; i += 256) {
                    int c = i >> 3, p8 = (i & 7) * 8;
                    cpa16(bd + (c * SBH + p8) * 2, inb + (size_t)c * HWC + h * 64 + p8);
                }
            }
        } else {
            for (int i = tid; i < 1024; i += 256) {
                int c = i >> 3, p8 = (i & 7) * 8;
                cpa16(sm + OFF_B0 + (c * SBH + p8) * 2, inb + (size_t)c * HWC + p8);
            }
        }
        const bf16* wt = W;
        for (int i = tid; i < 2048; i += 256) {
            int o = i >> 4, k8 = (i & 15) * 8;
            cpa16(sm + OFF_A0 + (o * SH + k8) * 2, wt + (size_t)o * KTOT + k8);
        }
        CP_COMMIT();
    }

    #pragma unroll
    for (int s = 0; s < NS; ++s) {
        const int kc = (KT == 2) ? s : 0;
        __syncthreads();
        if (s + 1 < NS) {
            const int kcn = (KT == 2) ? (s + 1) : 0;
            if (KT == 2 && kcn != kc) {
                char* bd = sm + ((kcn & 1) ? OFF_B1 : OFF_B0);
                for (int i = tid; i < 1024; i += 256) {
                    int c = i >> 3, p8 = (i & 7) * 8;
                    cpa16(bd + (c * SBH + p8) * 2, inb + (size_t)(kcn * 128 + c) * HWC + p8);
                }
            }
            const int sn = s + 1;
            const int ocb = (MODE == 1) ? ((sn & 1) * 256 + (sn >> 1) * 128)
                          : ((MODE == 0) ? sn * 128 : 0);
            const bf16* wt = W + (size_t)ocb * KTOT + kcn * 128;
            char* ad = sm + ((sn & 1) ? OFF_A1 : OFF_A0);
            for (int i = tid; i < 2048; i += 256) {
                int o = i >> 4, k8 = (i & 15) * 8;
                cpa16(ad + (o * SH + k8) * 2, wt + (size_t)o * KTOT + k8);
            }
            CP_COMMIT();
            CP_WAIT(1);
        } else {
            CP_WAIT(0);
        }
        __syncthreads();

        const int selb = ((MODE == 1) ? (s & 1) : 0) * NPX;
        if (MODE != 2 || s == 0) {
            #pragma unroll
            for (int h = 0; h < NPX; ++h)
                #pragma unroll
                for (int mi = 0; mi < 2; ++mi)
                    #pragma unroll
                    for (int j = 0; j < 4; ++j)
                        #pragma unroll
                        for (int q = 0; q < 4; ++q) acc[selb + h][mi][j][q] = 0.f;
        }

        {
            const uint32_t Ab = smb + ((s & 1) ? OFF_A1 : OFF_A0);
            const uint32_t aaddr = Ab + ((wm * 32 + a_m) * SH + a_k) * 2;
            #pragma unroll
            for (int h = 0; h < NPX; ++h) {
                const int bsel = (KT == 2) ? (kc & 1) : h;
                const uint32_t Bb = smb + (bsel ? OFF_B1 : OFF_B0);
                const uint32_t baddr = Bb + (b_k * SBH + b_n) * 2;
                float (*ac)[4][4] = acc[selb + h];
                #pragma unroll
                for (int k0 = 0; k0 < 128; k0 += 16) {
                    uint32_t a0[4], a1[4], b0[4], b1[4];
                    ldsm4 (a0, aaddr + k0 * 2);
                    ldsm4 (a1, aaddr + (16 * SH + k0) * 2);
                    ldsm4t(b0, baddr + k0 * SBH * 2);
                    ldsm4t(b1, baddr + (k0 * SBH + 16) * 2);
                    mma16(ac[0][0], a0, b0 + 0);
                    mma16(ac[0][1], a0, b0 + 2);
                    mma16(ac[0][2], a0, b1 + 0);
                    mma16(ac[0][3], a0, b1 + 2);
                    mma16(ac[1][0], a1, b0 + 0);
                    mma16(ac[1][1], a1, b0 + 2);
                    mma16(ac[1][2], a1, b1 + 0);
                    mma16(ac[1][3], a1, b1 + 2);
                }
            }
        }

        const int r0e = wm * 32 + (lane >> 2);
        const int c0e = wn * 32 + (lane & 3) * 2;

        if (MODE == 0 || (MODE == 1 && (s & 1))) {
            const int mt = (MODE == 1) ? (s >> 1) : s;
            bf16* st = (bf16*)(sm + ((s & 1) ? OFF_A1 : OFF_A0));
            #pragma unroll
            for (int h = 0; h < NPX; ++h) {
                __syncthreads();
                #pragma unroll
                for (int mi = 0; mi < 2; ++mi) {
                    int o = r0e + mi * 16;
                    if (MODE == 1) {
                        float bu1 = bs[mt * 128 + o],     bv1 = bs[256 + mt * 128 + o];
                        float bu2 = bs[mt * 128 + o + 8], bv2 = bs[256 + mt * 128 + o + 8];
                        float (*au)[4][4] = acc[0 * NPX + h];
                        float (*av)[4][4] = acc[1 * NPX + h];
                        #pragma unroll
                        for (int j = 0; j < 4; ++j) {
                            int c = c0e + j * 8;
                            float u0 = (au[mi][j][0] + bu1) * gelu_erf(av[mi][j][0] + bv1);
                            float u1 = (au[mi][j][1] + bu1) * gelu_erf(av[mi][j][1] + bv1);
                            float u2 = (au[mi][j][2] + bu2) * gelu_erf(av[mi][j][2] + bv2);
                            float u3 = (au[mi][j][3] + bu2) * gelu_erf(av[mi][j][3] + bv2);
                            *(__nv_bfloat162*)&st[o * SH + c] =
                                __halves2bfloat162(__float2bfloat16(u0), __float2bfloat16(u1));
                            *(__nv_bfloat162*)&st[(o + 8) * SH + c] =
                                __halves2bfloat162(__float2bfloat16(u2), __float2bfloat16(u3));
                        }
                    } else {
                        float b1v = bs[mt * 128 + o], b2v = bs[mt * 128 + o + 8];
                        float (*au)[4][4] = acc[selb + h];
                        #pragma unroll
                        for (int j = 0; j < 4; ++j) {
                            int c = c0e + j * 8;
                            *(__nv_bfloat162*)&st[o * SH + c] =
                                __halves2bfloat162(__float2bfloat16(au[mi][j][0] + b1v),
                                                   __float2bfloat16(au[mi][j][1] + b1v));
                            *(__nv_bfloat162*)&st[(o + 8) * SH + c] =
                                __halves2bfloat162(__float2bfloat16(au[mi][j][2] + b2v),
                                                   __float2bfloat16(au[mi][j][3] + b2v));
                        }
                    }
                }
                __syncthreads();
                for (int i = tid; i < 1024; i += 256) {
                    int o = i >> 3, p8 = (i & 7) * 8;
                    uint4 v = *(uint4*)&st[o * SH + p8];
                    *(uint4*)(outb + (size_t)b * OCOUT * HWC
                              + (size_t)(mt * 128 + o) * HWC + p0 + h * 64 + p8) = v;
                }
            }
        } else if (MODE == 2 && s == NS - 1) {
            __syncthreads();
            float* st = (float*)(sm + OFF_B0);
            #pragma unroll
            for (int mi = 0; mi < 2; ++mi) {
                int o = r0e + mi * 16;
                float b1v = bs[o], b2v = bs[o + 8];
                #pragma unroll
                for (int j = 0; j < 4; ++j) {
                    int c = c0e + j * 8;
                    st[o * 68 + c]           = acc[0][mi][j][0] + b1v;
                    st[o * 68 + c + 1]       = acc[0][mi][j][1] + b1v;
                    st[(o + 8) * 68 + c]     = acc[0][mi][j][2] + b2v;
                    st[(o + 8) * 68 + c + 1] = acc[0][mi][j][3] + b2v;
                }
            }
            __syncthreads();
            float scl = *scale_ptr;
            for (int i = tid; i < 2048; i += 256) {
                int o = i >> 4, p4 = (i & 15) * 4;
                float4 v = *(float4*)&st[o * 68 + p4];
                size_t oidx = (size_t)b * 128 * HWC + (size_t)o * HWC + p0 + p4;
                float4 rr = *(const float4*)(res + oidx);
                v.x = rr.x + scl * v.x; v.y = rr.y + scl * v.y;
                v.z = rr.z + scl * v.z; v.w = rr.w + scl * v.w;
                *(float4*)(out + oidx) = v;
                if (RMSOUT) *(float4*)&st[o * 68 + p4] = v;
            }
            if (RMSOUT) {
                __syncthreads();
                int px = tid & 63, part = tid >> 6;
                float ss = 0.f;
                #pragma unroll 8
                for (int c = part * 32; c < part * 32 + 32; ++c) {
                    float v = st[c * 68 + px]; ss += v * v;
                }
                rbuf[part * 64 + px] = ss;
                __syncthreads();
                if (tid < 64)
                    rbuf[tid] = rsqrtf((rbuf[tid] + rbuf[64 + tid] + rbuf[128 + tid]
                                      + rbuf[192 + tid]) * (1.0f / 128.0f) + 1e-6f);
                __syncthreads();
                for (int i = tid; i < 2048; i += 256) {
                    int o = i >> 4, p4 = (i & 15) * 4;
                    float sc = rsv[o], bb = rbv[o];
                    float4 v = *(float4*)&st[o * 68 + p4];
                    float n0 = rbuf[p4], n1 = rbuf[p4 + 1], n2 = rbuf[p4 + 2], n3 = rbuf[p4 + 3];
                    bf16* ob = outn + (size_t)b * 128 * HWC + (size_t)o * HWC + p0 + p4;
                    *(__nv_bfloat162*)ob =
                        __halves2bfloat162(__float2bfloat16(sc * v.x * n0 + bb),
                                           __float2bfloat16(sc * v.y * n1 + bb));
                    *(__nv_bfloat162*)(ob + 2) =
                        __halves2bfloat162(__float2bfloat16(sc * v.z * n2 + bb),
                                           __float2bfloat16(sc * v.w * n3 + bb));
                }
            }
        }
    }
}

// =====================================================================
// weight fp32 -> bf16
// =====================================================================
__global__ void wcvt_kernel(const float* p1, const float* p2, const float* p3,
                            const float* p4, const float* p5, const float* p6,
                            bf16* o)
{
    int i = blockIdx.x * 1024 + threadIdx.x * 4;
    const float* src; int base;
    if      (i < 65536)  { src = p1; base = 0; }
    else if (i < 98304)  { src = p2; base = 65536; }
    else if (i < 147456) { src = p3; base = 98304; }
    else if (i < 163840) { src = p4; base = 147456; }
    else if (i < 229376) { src = p5; base = 163840; }
    else                 { src = p6; base = 229376; }
    float4 v = *(const float4*)(src + (i - base));
    *(__nv_bfloat162*)(o + i)     = __halves2bfloat162(__float2bfloat16(v.x), __float2bfloat16(v.y));
    *(__nv_bfloat162*)(o + i + 2) = __halves2bfloat162(__float2bfloat16(v.z), __float2bfloat16(v.w));
}

// =====================================================================
// Depthwise 3x3 + bias + gated GELU
// =====================================================================
__global__ void __launch_bounds__(256)
dwgate_kernel(const bf16* __restrict__ a, const float* __restrict__ dw,
              const float* __restrict__ db, bf16* __restrict__ out)
{
    __shared__ float su[34 * 68], sv[34 * 68];
    int blk  = blockIdx.x;
    int tile = blk % 18;
    int cp   = (blk / 18) & 255;
    int b    = blk / (18 * 256);
    int ty0 = (tile / 3) * 32, tx0 = (tile % 3) * 64;
    const bf16* ua = a + ((size_t)b * 512 + cp) * HWC;
    const bf16* va = ua + (size_t)256 * HWC;

    #pragma unroll
    for (int it = 0; it < 5; ++it) {
        int i = threadIdx.x + it * 256;
        if (i < 34 * 34) {
            int ly = i / 34, px = i - ly * 34;
            int gy = ty0 + ly - 1;
            int gx = tx0 - 2 + px * 2;
            float2 uu = make_float2(0.f, 0.f), vv = make_float2(0.f, 0.f);
            if (((unsigned)gy < (unsigned)IMG) && ((unsigned)gx < (unsigned)IMG)) {
                int gi = gy * IMG + gx;
                uu = __bfloat1622float2(*(const __nv_bfloat162*)&ua[gi]);
                vv = __bfloat1622float2(*(const __nv_bfloat162*)&va[gi]);
            }
            *(float2*)&su[ly * 68 + px * 2] = uu;
            *(float2*)&sv[ly * 68 + px * 2] = vv;
        }
    }
    float wu[9], wv[9];
    #pragma unroll
    for (int i = 0; i < 9; ++i) {
        wu[i] = dw[cp * 9 + i];
        wv[i] = dw[(cp + 256) * 9 + i];
    }
    float bu = db[cp], bv = db[cp + 256];
    __syncthreads();

    int y0 = (threadIdx.x >> 4) * 2;
    int x0 = (threadIdx.x & 15) * 4;
    float U[4][8], V[4][8];
    #pragma unroll
    for (int r = 0; r < 4; ++r) {
        *(float4*)&U[r][0] = *(float4*)&su[(y0 + r) * 68 + x0];
        *(float4*)&U[r][4] = *(float4*)&su[(y0 + r) * 68 + x0 + 4];
        *(float4*)&V[r][0] = *(float4*)&sv[(y0 + r) * 68 + x0];
        *(float4*)&V[r][4] = *(float4*)&sv[(y0 + r) * 68 + x0 + 4];
    }

    bf16* ob = out + ((size_t)b * 256 + cp) * HWC;
    #pragma unroll
    for (int dy = 0; dy < 2; ++dy) {
        uint32_t pk[2];
        #pragma unroll
        for (int dp = 0; dp < 2; ++dp) {
            float r2[2];
            #pragma unroll
            for (int h = 0; h < 2; ++h) {
                int dx = dp * 2 + h;
                float u = bu, v = bv;
                #pragma unroll
                for (int i = 0; i < 3; ++i)
                    #pragma unroll
                    for (int j = 0; j < 3; ++j) {
                        u = fmaf(U[dy + i][dx + 1 + j], wu[i * 3 + j], u);
                        v = fmaf(V[dy + i][dx + 1 + j], wv[i * 3 + j], v);
                    }
                r2[h] = u * gelu_erf(v);
            }
            __nv_bfloat162 p2 = __halves2bfloat162(__float2bfloat16(r2[0]),
                                                   __float2bfloat16(r2[1]));
            pk[dp] = *(uint32_t*)&p2;
        }
        *(uint2*)&ob[(ty0 + y0 + dy) * IMG + tx0 + x0] = make_uint2(pk[0], pk[1]);
    }
}

// =====================================================================
// Attention: block = (window-pair, head), 128 threads. Adjacent windows
// share 32B sectors row-wise -> full sector utilization via L1 reuse.
// =====================================================================
__global__ void __launch_bounds__(128)
attn2_kernel(const bf16* __restrict__ qkv, const float* __restrict__ rpe,
             bf16* __restrict__ aog)
{
    __shared__ float Ks[2][64 * 36], Vs[2][64 * 36], rpe_s[225];
    __shared__ int lk[128];
    int wp = blockIdx.x >> 2, head = blockIdx.x & 3;
    int tid = threadIdx.x;
    int wsel = tid >> 6, t = tid & 63;
    int w = wp * 2 + wsel;
    int b = w / NWPB, wrem = w - b * NWPB;
    int wy = wrem / NWSIDE, wx = wrem - wy * NWSIDE;
    int qy = t >> 3, qx = t & 7;
    int myp;
    {
        int gh = wy * 8 + qy + 4; if (gh >= IMG) gh -= IMG;
        int gw = wx * 8 + qx + 4; if (gw >= IMG) gw -= IMG;
        myp = gh * IMG + gw;
    }
    {
        int gh = wy * 8 + qy, gw = wx * 8 + qx;
        int lh = gh < 184 ? 0 : (gh < 188 ? 1 : 2);
        int lw = gw < 184 ? 0 : (gw < 188 ? 1 : 2);
        lk[tid] = lh * 3 + lw;
    }
    for (int i = tid; i < 225; i += 128) rpe_s[i] = rpe[i * 4 + head];

    const bf16* qb = qkv + (size_t)b * 384 * HWC + (size_t)(head * 32) * HWC;
    const bf16* kb = qb + (size_t)128 * HWC;
    const bf16* vb = qb + (size_t)256 * HWC;
    float* Kw = Ks[wsel];
    float* Vw = Vs[wsel];
    float q[32];
    #pragma unroll
    for (int d = 0; d < 32; ++d) {
        q[d] = __bfloat162float(qb[(size_t)d * HWC + myp]) * 0.17677669529663687f;
        Kw[t * 36 + d] = __bfloat162float(kb[(size_t)d * HWC + myp]);
        Vw[t * 36 + d] = __bfloat162float(vb[(size_t)d * HWC + myp]);
    }
    int lab = lk[tid];
    __syncthreads();

    const int* lkw = lk + wsel * 64;
    float sc[64];
    float mx = -1e30f;
    #pragma unroll
    for (int kk = 0; kk < 64; ++kk) {
        const float4* kp = (const float4*)(Kw + kk * 36);
        float dot = 0.f;
        #pragma unroll
        for (int d4 = 0; d4 < 8; ++d4) {
            float4 kv = kp[d4];
            dot = fmaf(q[d4 * 4 + 0], kv.x, dot);
            dot = fmaf(q[d4 * 4 + 1], kv.y, dot);
            dot = fmaf(q[d4 * 4 + 2], kv.z, dot);
            dot = fmaf(q[d4 * 4 + 3], kv.w, dot);
        }
        int ky = kk >> 3, kx = kk & 7;
        dot += rpe_s[(qy - ky + 7) * 15 + (qx - kx + 7)];
        if (lab != lkw[kk]) dot = -1e30f;
        sc[kk] = dot;
        mx = fmaxf(mx, dot);
    }
    float sum = 0.f;
    #pragma unroll
    for (int kk = 0; kk < 64; ++kk) {
        float e = __expf(sc[kk] - mx);
        sc[kk] = e; sum += e;
    }
    float inv = 1.0f / sum;
    float acc[32];
    #pragma unroll
    for (int d = 0; d < 32; ++d) acc[d] = 0.f;
    #pragma unroll
    for (int kk = 0; kk < 64; ++kk) {
        float p = sc[kk];
        const float4* vp = (const float4*)(Vw + kk * 36);
        #pragma unroll
        for (int d4 = 0; d4 < 8; ++d4) {
            float4 vv = vp[d4];
            acc[d4 * 4 + 0] = fmaf(p, vv.x, acc[d4 * 4 + 0]);
            acc[d4 * 4 + 1] = fmaf(p, vv.y, acc[d4 * 4 + 1]);
            acc[d4 * 4 + 2] = fmaf(p, vv.z, acc[d4 * 4 + 2]);
            acc[d4 * 4 + 3] = fmaf(p, vv.w, acc[d4 * 4 + 3]);
        }
    }
    size_t cb = (size_t)b * 128 * HWC + (size_t)(head * 32) * HWC;
    #pragma unroll
    for (int d = 0; d < 32; ++d)
        aog[cb + (size_t)d * HWC + myp] = __float2bfloat16(acc[d] * inv);
}

// =====================================================================
extern "C" void kernel_launch(void* const* d_in, const int* in_sizes, int n_in,
                              void* d_out, int out_size)
{
    const float* x      = (const float*)d_in[0];
    const float* cg_s   = (const float*)d_in[1];
    const float* cg_b   = (const float*)d_in[2];
    const float* pw1_w  = (const float*)d_in[3];
    const float* pw1_b  = (const float*)d_in[4];
    const float* dw_w   = (const float*)d_in[5];
    const float* dw_b   = (const float*)d_in[6];
    const float* pw2_w  = (const float*)d_in[7];
    const float* pw2_b  = (const float*)d_in[8];
    const float* beta   = (const float*)d_in[9];
    const float* at_s   = (const float*)d_in[10];
    const float* at_b   = (const float*)d_in[11];
    const float* qkv_w  = (const float*)d_in[12];
    const float* qkv_b  = (const float*)d_in[13];
    const float* rpe    = (const float*)d_in[14];
    const float* proj_w = (const float*)d_in[15];
    const float* proj_b = (const float*)d_in[16];
    const float* alpha  = (const float*)d_in[17];
    const float* ff_s   = (const float*)d_in[18];
    const float* ff_b   = (const float*)d_in[19];
    const float* fc1_w  = (const float*)d_in[20];
    const float* fc1_b  = (const float*)d_in[21];
    const float* fc2_w  = (const float*)d_in[22];
    const float* fc2_b  = (const float*)d_in[23];
    const float* gamma  = (const float*)d_in[24];
    float* out = (float*)d_out;

    bf16 *wbf, *a512, *g256, *qkvb, *aob, *x1n, *x2n;
    float *x1, *x2;
    cudaGetSymbolAddress((void**)&wbf,  g_wbf);
    cudaGetSymbolAddress((void**)&a512, g_a512);
    cudaGetSymbolAddress((void**)&g256, g_g256);
    cudaGetSymbolAddress((void**)&qkvb, g_qkv);
    cudaGetSymbolAddress((void**)&aob,  g_ao);
    cudaGetSymbolAddress((void**)&x1n,  g_x1n);
    cudaGetSymbolAddress((void**)&x2n,  g_x2n);
    cudaGetSymbolAddress((void**)&x1,   g_x1);
    cudaGetSymbolAddress((void**)&x2,   g_x2);

    cudaFuncSetAttribute(tc_gemm<1, 4, 0, false, true , 2>, cudaFuncAttributeMaxDynamicSharedMemorySize, SMB);
    cudaFuncSetAttribute(tc_gemm<1, 3, 0, false, false, 2>, cudaFuncAttributeMaxDynamicSharedMemorySize, SMB);
    cudaFuncSetAttribute(tc_gemm<2, 1, 2, true , false, 1>, cudaFuncAttributeMaxDynamicSharedMemorySize, SMB);
    cudaFuncSetAttribute(tc_gemm<1, 1, 2, true , false, 1>, cudaFuncAttributeMaxDynamicSharedMemorySize, SMB);
    cudaFuncSetAttribute(tc_gemm<1, 2, 1, false, false, 1>, cudaFuncAttributeMaxDynamicSharedMemorySize, SMB);
    cudaFuncSetAttribute(tc_gemm<2, 1, 2, false, false, 1>, cudaFuncAttributeMaxDynamicSharedMemorySize, SMB);

    const int NPB  = 1152;   // 64-px tiles
    const int NPB2 = 576;    // 128-px tiles

    // ---- prep ----
    wcvt_kernel<<<256, 256>>>(pw1_w, pw2_w, qkv_w, proj_w, fc1_w, fc2_w, wbf);

    // ---- conv gated block (RMS fused into pw1, NPX=2) ----
    tc_gemm<1, 4, 0, false, true, 2><<<NPB2, 256, SMB>>>(
        nullptr, wbf + 0, pw1_b, nullptr, nullptr, nullptr, a512, nullptr,
        cg_s, cg_b, x);
    dwgate_kernel<<<2 * 256 * 18, 256>>>(a512, dw_w, dw_b, g256);
    tc_gemm<2, 1, 2, true, false, 1><<<NPB, 256, SMB>>>(
        g256, wbf + 65536, pw2_b, x, beta, x1, nullptr, x1n, at_s, at_b, nullptr);

    // ---- window attention (qkv NPX=2; attn window-pair blocks) ----
    tc_gemm<1, 3, 0, false, false, 2><<<NPB2, 256, SMB>>>(
        x1n, wbf + 98304, qkv_b, nullptr, nullptr, nullptr, qkvb, nullptr,
        nullptr, nullptr, nullptr);
    attn2_kernel<<<(NWTOT / 2) * 4, 128>>>(qkvb, rpe, aob);
    tc_gemm<1, 1, 2, true, false, 1><<<NPB, 256, SMB>>>(
        aob, wbf + 147456, proj_b, x1, alpha, x2, nullptr, x2n, ff_s, ff_b, nullptr);

    // ---- gated FFN ----
    tc_gemm<1, 2, 1, false, false, 1><<<NPB, 256, SMB>>>(
        x2n, wbf + 163840, fc1_b, nullptr, nullptr, nullptr, g256, nullptr,
        nullptr, nullptr, nullptr);
    tc_gemm<2, 1, 2, false, false, 1><<<NPB, 256, SMB>>>(
        g256, wbf + 229376, fc2_b, x2, gamma, out, nullptr, nullptr,
        nullptr, nullptr, nullptr);
}

// round 16
// speedup vs baseline: 1.0273x; 1.0273x over previous
#include <cuda_runtime.h>
#include <cuda_bf16.h>
#include <math.h>
#include <stdint.h>

#define IMG 192
#define HWC (192*192)
#define NWSIDE 24
#define NWPB 576
#define NWTOT 1152
typedef __nv_bfloat16 bf16;

// ---------------- scratch (device globals) ----------------
static __device__ bf16  g_wbf [262144];
static __device__ bf16  g_a512[(size_t)2*512*HWC];
static __device__ bf16  g_g256[(size_t)2*256*HWC];
static __device__ bf16  g_qkv [(size_t)2*384*HWC];
static __device__ bf16  g_ao  [(size_t)2*128*HWC];
static __device__ bf16  g_x1n [(size_t)2*128*HWC];
static __device__ bf16  g_x2n [(size_t)2*128*HWC];
static __device__ float g_x1  [(size_t)2*128*HWC];
static __device__ float g_x2  [(size_t)2*128*HWC];

// Fast erf-GELU (A&S 7.1.26, |err|<1.5e-7)
__device__ __forceinline__ float gelu_erf(float v) {
    float z  = fabsf(v) * 0.70710678118654752f;
    float t  = __fdividef(1.0f, fmaf(0.3275911f, z, 1.0f));
    float p  = fmaf(t, 1.061405429f, -1.453152027f);
    p = fmaf(t, p, 1.421413741f);
    p = fmaf(t, p, -0.284496736f);
    p = fmaf(t, p, 0.254829592f);
    float e  = p * t * __expf(-z * z);
    float er = 1.0f - e;
    er = copysignf(er, v);
    return 0.5f * v * (1.0f + er);
}
__device__ __forceinline__ uint32_t smem_u32(const void* p) {
    uint32_t a;
    asm("{ .reg .u64 t; cvta.to.shared.u64 t, %1; cvt.u32.u64 %0, t; }" : "=r"(a) : "l"(p));
    return a;
}
__device__ __forceinline__ void cpa16(void* dst, const void* src) {
    uint32_t d = smem_u32(dst);
    asm volatile("cp.async.cg.shared.global [%0], [%1], 16;" :: "r"(d), "l"(src) : "memory");
}
#define CP_COMMIT() asm volatile("cp.async.commit_group;" ::: "memory")
#define CP_WAIT(n)  asm volatile("cp.async.wait_group %0;" :: "n"(n) : "memory")

__device__ __forceinline__ void ldsm4(uint32_t* r, uint32_t addr) {
    asm volatile("ldmatrix.sync.aligned.m8n8.x4.shared.b16 {%0,%1,%2,%3}, [%4];"
        : "=r"(r[0]), "=r"(r[1]), "=r"(r[2]), "=r"(r[3]) : "r"(addr));
}
__device__ __forceinline__ void ldsm4t(uint32_t* r, uint32_t addr) {
    asm volatile("ldmatrix.sync.aligned.m8n8.x4.trans.shared.b16 {%0,%1,%2,%3}, [%4];"
        : "=r"(r[0]), "=r"(r[1]), "=r"(r[2]), "=r"(r[3]) : "r"(addr));
}
__device__ __forceinline__ void mma16(float* c, const uint32_t* a, const uint32_t* b) {
    asm volatile("mma.sync.aligned.m16n8k16.row.col.f32.bf16.bf16.f32 "
        "{%0,%1,%2,%3}, {%4,%5,%6,%7}, {%8,%9}, {%0,%1,%2,%3};"
        : "+f"(c[0]), "+f"(c[1]), "+f"(c[2]), "+f"(c[3])
        : "r"(a[0]), "r"(a[1]), "r"(a[2]), "r"(a[3]), "r"(b[0]), "r"(b[1]));
}

// smem byte offsets — N=64px tiles, 2 CTAs/SM
#define SH  136
#define SBH 72
#define OFF_A0   0
#define OFF_A1   34816        // also fp32 RMSIN staging [128][68]
#define OFF_B0   69632
#define OFF_B1   88064
#define OFF_BIAS 106496
#define OFF_RS   108544
#define OFF_RB   109056
#define OFF_RBUF 109568
#define SMB      110592

// =====================================================================
// bf16 mma GEMM. NPX pixel tiles per block share streamed A weights
// (KT==1 only: uses B0/B1 as the per-tile input buffers).
// MODE2 epilogue loops the NPX halves through one staging region.
// =====================================================================
template<int KT, int MT, int MODE, bool RMSOUT, bool RMSIN, int NPX>
__global__ void __launch_bounds__(256, 2)
tc_gemm(const bf16* __restrict__ in, const bf16* __restrict__ W,
        const float* __restrict__ bias,
        const float* __restrict__ res, const float* __restrict__ scale_ptr,
        float* __restrict__ out, bf16* __restrict__ outb,
        bf16* __restrict__ outn,
        const float* __restrict__ rs2, const float* __restrict__ rb2,
        const float* __restrict__ inf)
{
    constexpr int NSUB  = (MODE == 1) ? 2 : 1;
    constexpr int NS    = KT * MT * NSUB;
    constexpr int KTOT  = KT * 128;
    constexpr int OCOUT = (MODE == 1) ? 256 : MT * 128;
    constexpr int NBIAS = (MODE == 1) ? 512 : MT * 128;
    constexpr int NACC  = (MODE == 1) ? 2 : 1;
    constexpr int SLOTS = NACC * NPX;

    extern __shared__ char sm[];
    float* bs   = (float*)(sm + OFF_BIAS);
    float* rsv  = (float*)(sm + OFF_RS);
    float* rbv  = (float*)(sm + OFF_RB);
    float* rbuf = (float*)(sm + OFF_RBUF);
    const uint32_t smb = smem_u32(sm);

    const int tid = threadIdx.x, lane = tid & 31, wid = tid >> 5;
    const int wm = wid & 3, wn = wid >> 2;
    const int gp = blockIdx.x * (64 * NPX);
    const int b  = gp / HWC;
    const int p0 = gp - b * HWC;
    const bf16* inb = RMSIN ? nullptr : (in + (size_t)b * KTOT * HWC + p0);

    for (int i = tid; i < NBIAS; i += 256) bs[i] = bias[i];
    if (RMSOUT) for (int i = tid; i < 128; i += 256) { rsv[i] = rs2[i]; rbv[i] = rb2[i]; }

    const int a_m = (lane & 7) + ((lane >> 3) & 1) * 8;
    const int a_k = (lane >> 4) * 8;
    const int b_k = (lane & 7) + ((lane >> 3) & 1) * 8;
    const int b_n = wn * 32 + (lane >> 4) * 8;

    float acc[SLOTS][2][4][4];

    if (RMSIN) {
        float* stg = (float*)(sm + OFF_A1);
        #pragma unroll
        for (int h = 0; h < NPX; ++h) {
            const float* xf = inf + (size_t)b * 128 * HWC + p0 + h * 64;
            for (int i = tid; i < 2048; i += 256) {
                int c = i >> 4, p4 = (i & 15) * 4;
                cpa16(stg + c * 68 + p4, xf + (size_t)c * HWC + p4);
            }
            CP_COMMIT();
            if (h == NPX - 1) {
                const bf16* wt = W;
                for (int i = tid; i < 2048; i += 256) {
                    int o = i >> 4, k8 = (i & 15) * 8;
                    cpa16(sm + OFF_A0 + (o * SH + k8) * 2, wt + (size_t)o * KTOT + k8);
                }
                CP_COMMIT();
                CP_WAIT(1);
            } else {
                CP_WAIT(0);
            }
            __syncthreads();
            int px = tid & 63, part = tid >> 6;
            float ss = 0.f;
            #pragma unroll 8
            for (int c = part * 32; c < part * 32 + 32; ++c) {
                float v = stg[c * 68 + px]; ss += v * v;
            }
            rbuf[part * 64 + px] = ss;
            __syncthreads();
            if (tid < 64)
                rbuf[tid] = rsqrtf((rbuf[tid] + rbuf[64 + tid] + rbuf[128 + tid]
                                  + rbuf[192 + tid]) * (1.0f / 128.0f) + 1e-6f);
            __syncthreads();
            bf16* Bh = (bf16*)(sm + (h ? OFF_B1 : OFF_B0));
            for (int i = tid; i < 4096; i += 256) {
                int c = i >> 5, p2 = (i & 31) * 2;
                float sc = rs2[c], bb = rb2[c];
                float v0 = sc * stg[c * 68 + p2]     * rbuf[p2]     + bb;
                float v1 = sc * stg[c * 68 + p2 + 1] * rbuf[p2 + 1] + bb;
                *(__nv_bfloat162*)&Bh[c * SBH + p2] =
                    __halves2bfloat162(__float2bfloat16(v0), __float2bfloat16(v1));
            }
            __syncthreads();
        }
    } else {
        if (KT == 1) {
            #pragma unroll
            for (int h = 0; h < NPX; ++h) {
                char* bd = sm + (h ? OFF_B1 : OFF_B0);
                for (int i = tid; i < 1024; i += 256) {
                    int c = i >> 3, p8 = (i & 7) * 8;
                    cpa16(bd + (c * SBH + p8) * 2, inb + (size_t)c * HWC + h * 64 + p8);
                }
            }
        } else {
            for (int i = tid; i < 1024; i += 256) {
                int c = i >> 3, p8 = (i & 7) * 8;
                cpa16(sm + OFF_B0 + (c * SBH + p8) * 2, inb + (size_t)c * HWC + p8);
            }
        }
        const bf16* wt = W;
        for (int i = tid; i < 2048; i += 256) {
            int o = i >> 4, k8 = (i & 15) * 8;
            cpa16(sm + OFF_A0 + (o * SH + k8) * 2, wt + (size_t)o * KTOT + k8);
        }
        CP_COMMIT();
    }

    #pragma unroll
    for (int s = 0; s < NS; ++s) {
        const int kc = (KT == 2) ? s : 0;
        __syncthreads();
        if (s + 1 < NS) {
            const int kcn = (KT == 2) ? (s + 1) : 0;
            if (KT == 2 && kcn != kc) {
                char* bd = sm + ((kcn & 1) ? OFF_B1 : OFF_B0);
                for (int i = tid; i < 1024; i += 256) {
                    int c = i >> 3, p8 = (i & 7) * 8;
                    cpa16(bd + (c * SBH + p8) * 2, inb + (size_t)(kcn * 128 + c) * HWC + p8);
                }
            }
            const int sn = s + 1;
            const int ocb = (MODE == 1) ? ((sn & 1) * 256 + (sn >> 1) * 128)
                          : ((MODE == 0) ? sn * 128 : 0);
            const bf16* wt = W + (size_t)ocb * KTOT + kcn * 128;
            char* ad = sm + ((sn & 1) ? OFF_A1 : OFF_A0);
            for (int i = tid; i < 2048; i += 256) {
                int o = i >> 4, k8 = (i & 15) * 8;
                cpa16(ad + (o * SH + k8) * 2, wt + (size_t)o * KTOT + k8);
            }
            CP_COMMIT();
            CP_WAIT(1);
        } else {
            CP_WAIT(0);
        }
        __syncthreads();

        const int selb = ((MODE == 1) ? (s & 1) : 0) * NPX;
        if (MODE != 2 || s == 0) {
            #pragma unroll
            for (int h = 0; h < NPX; ++h)
                #pragma unroll
                for (int mi = 0; mi < 2; ++mi)
                    #pragma unroll
                    for (int j = 0; j < 4; ++j)
                        #pragma unroll
                        for (int q = 0; q < 4; ++q) acc[selb + h][mi][j][q] = 0.f;
        }

        {
            const uint32_t Ab = smb + ((s & 1) ? OFF_A1 : OFF_A0);
            const uint32_t aaddr = Ab + ((wm * 32 + a_m) * SH + a_k) * 2;
            #pragma unroll
            for (int h = 0; h < NPX; ++h) {
                const int bsel = (KT == 2) ? (kc & 1) : h;
                const uint32_t Bb = smb + (bsel ? OFF_B1 : OFF_B0);
                const uint32_t baddr = Bb + (b_k * SBH + b_n) * 2;
                float (*ac)[4][4] = acc[selb + h];
                #pragma unroll
                for (int k0 = 0; k0 < 128; k0 += 16) {
                    uint32_t a0[4], a1[4], b0[4], b1[4];
                    ldsm4 (a0, aaddr + k0 * 2);
                    ldsm4 (a1, aaddr + (16 * SH + k0) * 2);
                    ldsm4t(b0, baddr + k0 * SBH * 2);
                    ldsm4t(b1, baddr + (k0 * SBH + 16) * 2);
                    mma16(ac[0][0], a0, b0 + 0);
                    mma16(ac[0][1], a0, b0 + 2);
                    mma16(ac[0][2], a0, b1 + 0);
                    mma16(ac[0][3], a0, b1 + 2);
                    mma16(ac[1][0], a1, b0 + 0);
                    mma16(ac[1][1], a1, b0 + 2);
                    mma16(ac[1][2], a1, b1 + 0);
                    mma16(ac[1][3], a1, b1 + 2);
                }
            }
        }

        const int r0e = wm * 32 + (lane >> 2);
        const int c0e = wn * 32 + (lane & 3) * 2;

        if (MODE == 0 || (MODE == 1 && (s & 1))) {
            const int mt = (MODE == 1) ? (s >> 1) : s;
            bf16* st = (bf16*)(sm + ((s & 1) ? OFF_A1 : OFF_A0));
            #pragma unroll
            for (int h = 0; h < NPX; ++h) {
                __syncthreads();
                #pragma unroll
                for (int mi = 0; mi < 2; ++mi) {
                    int o = r0e + mi * 16;
                    if (MODE == 1) {
                        float bu1 = bs[mt * 128 + o],     bv1 = bs[256 + mt * 128 + o];
                        float bu2 = bs[mt * 128 + o + 8], bv2 = bs[256 + mt * 128 + o + 8];
                        float (*au)[4][4] = acc[0 * NPX + h];
                        float (*av)[4][4] = acc[1 * NPX + h];
                        #pragma unroll
                        for (int j = 0; j < 4; ++j) {
                            int c = c0e + j * 8;
                            float u0 = (au[mi][j][0] + bu1) * gelu_erf(av[mi][j][0] + bv1);
                            float u1 = (au[mi][j][1] + bu1) * gelu_erf(av[mi][j][1] + bv1);
                            float u2 = (au[mi][j][2] + bu2) * gelu_erf(av[mi][j][2] + bv2);
                            float u3 = (au[mi][j][3] + bu2) * gelu_erf(av[mi][j][3] + bv2);
                            *(__nv_bfloat162*)&st[o * SH + c] =
                                __halves2bfloat162(__float2bfloat16(u0), __float2bfloat16(u1));
                            *(__nv_bfloat162*)&st[(o + 8) * SH + c] =
                                __halves2bfloat162(__float2bfloat16(u2), __float2bfloat16(u3));
                        }
                    } else {
                        float b1v = bs[mt * 128 + o], b2v = bs[mt * 128 + o + 8];
                        float (*au)[4][4] = acc[selb + h];
                        #pragma unroll
                        for (int j = 0; j < 4; ++j) {
                            int c = c0e + j * 8;
                            *(__nv_bfloat162*)&st[o * SH + c] =
                                __halves2bfloat162(__float2bfloat16(au[mi][j][0] + b1v),
                                                   __float2bfloat16(au[mi][j][1] + b1v));
                            *(__nv_bfloat162*)&st[(o + 8) * SH + c] =
                                __halves2bfloat162(__float2bfloat16(au[mi][j][2] + b2v),
                                                   __float2bfloat16(au[mi][j][3] + b2v));
                        }
                    }
                }
                __syncthreads();
                for (int i = tid; i < 1024; i += 256) {
                    int o = i >> 3, p8 = (i & 7) * 8;
                    uint4 v = *(uint4*)&st[o * SH + p8];
                    *(uint4*)(outb + (size_t)b * OCOUT * HWC
                              + (size_t)(mt * 128 + o) * HWC + p0 + h * 64 + p8) = v;
                }
            }
        } else if (MODE == 2 && s == NS - 1) {
            // MODE2 epilogue: loop NPX halves through one fp32 staging region
            float* st = (float*)(sm + OFF_B0);   // [128][68] spans B0..B1
            float scl = *scale_ptr;
            #pragma unroll
            for (int h = 0; h < NPX; ++h) {
                __syncthreads();   // inputs consumed / previous h done
                #pragma unroll
                for (int mi = 0; mi < 2; ++mi) {
                    int o = r0e + mi * 16;
                    float b1v = bs[o], b2v = bs[o + 8];
                    float (*au)[4][4] = acc[h];
                    #pragma unroll
                    for (int j = 0; j < 4; ++j) {
                        int c = c0e + j * 8;
                        st[o * 68 + c]           = au[mi][j][0] + b1v;
                        st[o * 68 + c + 1]       = au[mi][j][1] + b1v;
                        st[(o + 8) * 68 + c]     = au[mi][j][2] + b2v;
                        st[(o + 8) * 68 + c + 1] = au[mi][j][3] + b2v;
                    }
                }
                __syncthreads();
                for (int i = tid; i < 2048; i += 256) {
                    int o = i >> 4, p4 = (i & 15) * 4;
                    float4 v = *(float4*)&st[o * 68 + p4];
                    size_t oidx = (size_t)b * 128 * HWC + (size_t)o * HWC + p0 + h * 64 + p4;
                    float4 rr = *(const float4*)(res + oidx);
                    v.x = rr.x + scl * v.x; v.y = rr.y + scl * v.y;
                    v.z = rr.z + scl * v.z; v.w = rr.w + scl * v.w;
                    *(float4*)(out + oidx) = v;
                    if (RMSOUT) *(float4*)&st[o * 68 + p4] = v;
                }
                if (RMSOUT) {
                    __syncthreads();
                    int px = tid & 63, part = tid >> 6;
                    float ss = 0.f;
                    #pragma unroll 8
                    for (int c = part * 32; c < part * 32 + 32; ++c) {
                        float v = st[c * 68 + px]; ss += v * v;
                    }
                    rbuf[part * 64 + px] = ss;
                    __syncthreads();
                    if (tid < 64)
                        rbuf[tid] = rsqrtf((rbuf[tid] + rbuf[64 + tid] + rbuf[128 + tid]
                                          + rbuf[192 + tid]) * (1.0f / 128.0f) + 1e-6f);
                    __syncthreads();
                    for (int i = tid; i < 2048; i += 256) {
                        int o = i >> 4, p4 = (i & 15) * 4;
                        float sc = rsv[o], bb = rbv[o];
                        float4 v = *(float4*)&st[o * 68 + p4];
                        float n0 = rbuf[p4], n1 = rbuf[p4 + 1], n2 = rbuf[p4 + 2], n3 = rbuf[p4 + 3];
                        bf16* ob = outn + (size_t)b * 128 * HWC + (size_t)o * HWC + p0 + h * 64 + p4;
                        *(__nv_bfloat162*)ob =
                            __halves2bfloat162(__float2bfloat16(sc * v.x * n0 + bb),
                                               __float2bfloat16(sc * v.y * n1 + bb));
                        *(__nv_bfloat162*)(ob + 2) =
                            __halves2bfloat162(__float2bfloat16(sc * v.z * n2 + bb),
                                               __float2bfloat16(sc * v.w * n3 + bb));
                    }
                }
            }
        }
    }
}

// =====================================================================
// weight fp32 -> bf16
// =====================================================================
__global__ void wcvt_kernel(const float* p1, const float* p2, const float* p3,
                            const float* p4, const float* p5, const float* p6,
                            bf16* o)
{
    int i = blockIdx.x * 1024 + threadIdx.x * 4;
    const float* src; int base;
    if      (i < 65536)  { src = p1; base = 0; }
    else if (i < 98304)  { src = p2; base = 65536; }
    else if (i < 147456) { src = p3; base = 98304; }
    else if (i < 163840) { src = p4; base = 147456; }
    else if (i < 229376) { src = p5; base = 163840; }
    else                 { src = p6; base = 229376; }
    float4 v = *(const float4*)(src + (i - base));
    *(__nv_bfloat162*)(o + i)     = __halves2bfloat162(__float2bfloat16(v.x), __float2bfloat16(v.y));
    *(__nv_bfloat162*)(o + i + 2) = __halves2bfloat162(__float2bfloat16(v.z), __float2bfloat16(v.w));
}

// =====================================================================
// Depthwise 3x3 + bias + gated GELU
// =====================================================================
__global__ void __launch_bounds__(256)
dwgate_kernel(const bf16* __restrict__ a, const float* __restrict__ dw,
              const float* __restrict__ db, bf16* __restrict__ out)
{
    __shared__ float su[34 * 68], sv[34 * 68];
    int blk  = blockIdx.x;
    int tile = blk % 18;
    int cp   = (blk / 18) & 255;
    int b    = blk / (18 * 256);
    int ty0 = (tile / 3) * 32, tx0 = (tile % 3) * 64;
    const bf16* ua = a + ((size_t)b * 512 + cp) * HWC;
    const bf16* va = ua + (size_t)256 * HWC;

    #pragma unroll
    for (int it = 0; it < 5; ++it) {
        int i = threadIdx.x + it * 256;
        if (i < 34 * 34) {
            int ly = i / 34, px = i - ly * 34;
            int gy = ty0 + ly - 1;
            int gx = tx0 - 2 + px * 2;
            float2 uu = make_float2(0.f, 0.f), vv = make_float2(0.f, 0.f);
            if (((unsigned)gy < (unsigned)IMG) && ((unsigned)gx < (unsigned)IMG)) {
                int gi = gy * IMG + gx;
                uu = __bfloat1622float2(*(const __nv_bfloat162*)&ua[gi]);
                vv = __bfloat1622float2(*(const __nv_bfloat162*)&va[gi]);
            }
            *(float2*)&su[ly * 68 + px * 2] = uu;
            *(float2*)&sv[ly * 68 + px * 2] = vv;
        }
    }
    float wu[9], wv[9];
    #pragma unroll
    for (int i = 0; i < 9; ++i) {
        wu[i] = dw[cp * 9 + i];
        wv[i] = dw[(cp + 256) * 9 + i];
    }
    float bu = db[cp], bv = db[cp + 256];
    __syncthreads();

    int y0 = (threadIdx.x >> 4) * 2;
    int x0 = (threadIdx.x & 15) * 4;
    float U[4][8], V[4][8];
    #pragma unroll
    for (int r = 0; r < 4; ++r) {
        *(float4*)&U[r][0] = *(float4*)&su[(y0 + r) * 68 + x0];
        *(float4*)&U[r][4] = *(float4*)&su[(y0 + r) * 68 + x0 + 4];
        *(float4*)&V[r][0] = *(float4*)&sv[(y0 + r) * 68 + x0];
        *(float4*)&V[r][4] = *(float4*)&sv[(y0 + r) * 68 + x0 + 4];
    }

    bf16* ob = out + ((size_t)b * 256 + cp) * HWC;
    #pragma unroll
    for (int dy = 0; dy < 2; ++dy) {
        uint32_t pk[2];
        #pragma unroll
        for (int dp = 0; dp < 2; ++dp) {
            float r2[2];
            #pragma unroll
            for (int h = 0; h < 2; ++h) {
                int dx = dp * 2 + h;
                float u = bu, v = bv;
                #pragma unroll
                for (int i = 0; i < 3; ++i)
                    #pragma unroll
                    for (int j = 0; j < 3; ++j) {
                        u = fmaf(U[dy + i][dx + 1 + j], wu[i * 3 + j], u);
                        v = fmaf(V[dy + i][dx + 1 + j], wv[i * 3 + j], v);
                    }
                r2[h] = u * gelu_erf(v);
            }
            __nv_bfloat162 p2 = __halves2bfloat162(__float2bfloat16(r2[0]),
                                                   __float2bfloat16(r2[1]));
            pk[dp] = *(uint32_t*)&p2;
        }
        *(uint2*)&ob[(ty0 + y0 + dy) * IMG + tx0 + x0] = make_uint2(pk[0], pk[1]);
    }
}

// =====================================================================
// Attention (round-14 form: 64 threads per (window, head))
// =====================================================================
__global__ void __launch_bounds__(64)
attn2_kernel(const bf16* __restrict__ qkv, const float* __restrict__ rpe,
             bf16* __restrict__ aog)
{
    __shared__ float Ks[64 * 36], Vs[64 * 36], rpe_s[225];
    __shared__ int pix[64], lk[64];
    int w = blockIdx.x >> 2, head = blockIdx.x & 3;
    int tid = threadIdx.x;
    int b = w / NWPB, wrem = w - b * NWPB;
    int wy = wrem / NWSIDE, wx = wrem - wy * NWSIDE;
    int qy = tid >> 3, qx = tid & 7;
    {
        int gh = wy * 8 + qy + 4; if (gh >= IMG) gh -= IMG;
        int gw = wx * 8 + qx + 4; if (gw >= IMG) gw -= IMG;
        pix[tid] = gh * IMG + gw;
    }
    {
        int gh = wy * 8 + qy, gw = wx * 8 + qx;
        int lh = gh < 184 ? 0 : (gh < 188 ? 1 : 2);
        int lw = gw < 184 ? 0 : (gw < 188 ? 1 : 2);
        lk[tid] = lh * 3 + lw;
    }
    for (int i = tid; i < 225; i += 64) rpe_s[i] = rpe[i * 4 + head];
    __syncthreads();

    const bf16* qb = qkv + (size_t)b * 384 * HWC + (size_t)(head * 32) * HWC;
    const bf16* kb = qb + (size_t)128 * HWC;
    const bf16* vb = qb + (size_t)256 * HWC;
    int myp = pix[tid];
    float q[32];
    #pragma unroll
    for (int d = 0; d < 32; ++d) {
        q[d] = __bfloat162float(qb[(size_t)d * HWC + myp]) * 0.17677669529663687f;
        Ks[tid * 36 + d] = __bfloat162float(kb[(size_t)d * HWC + myp]);
        Vs[tid * 36 + d] = __bfloat162float(vb[(size_t)d * HWC + myp]);
    }
    int lab = lk[tid];
    __syncthreads();

    float sc[64];
    float mx = -1e30f;
    #pragma unroll
    for (int kk = 0; kk < 64; ++kk) {
        const float4* kp = (const float4*)(Ks + kk * 36);
        float dot = 0.f;
        #pragma unroll
        for (int d4 = 0; d4 < 8; ++d4) {
            float4 kv = kp[d4];
            dot = fmaf(q[d4 * 4 + 0], kv.x, dot);
            dot = fmaf(q[d4 * 4 + 1], kv.y, dot);
            dot = fmaf(q[d4 * 4 + 2], kv.z, dot);
            dot = fmaf(q[d4 * 4 + 3], kv.w, dot);
        }
        int ky = kk >> 3, kx = kk & 7;
        dot += rpe_s[(qy - ky + 7) * 15 + (qx - kx + 7)];
        if (lab != lk[kk]) dot = -1e30f;
        sc[kk] = dot;
        mx = fmaxf(mx, dot);
    }
    float sum = 0.f;
    #pragma unroll
    for (int kk = 0; kk < 64; ++kk) {
        float e = __expf(sc[kk] - mx);
        sc[kk] = e; sum += e;
    }
    float inv = 1.0f / sum;
    float acc[32];
    #pragma unroll
    for (int d = 0; d < 32; ++d) acc[d] = 0.f;
    #pragma unroll
    for (int kk = 0; kk < 64; ++kk) {
        float p = sc[kk];
        const float4* vp = (const float4*)(Vs + kk * 36);
        #pragma unroll
        for (int d4 = 0; d4 < 8; ++d4) {
            float4 vv = vp[d4];
            acc[d4 * 4 + 0] = fmaf(p, vv.x, acc[d4 * 4 + 0]);
            acc[d4 * 4 + 1] = fmaf(p, vv.y, acc[d4 * 4 + 1]);
            acc[d4 * 4 + 2] = fmaf(p, vv.z, acc[d4 * 4 + 2]);
            acc[d4 * 4 + 3] = fmaf(p, vv.w, acc[d4 * 4 + 3]);
        }
    }
    size_t cb = (size_t)b * 128 * HWC + (size_t)(head * 32) * HWC;
    #pragma unroll
    for (int d = 0; d < 32; ++d)
        aog[cb + (size_t)d * HWC + myp] = __float2bfloat16(acc[d] * inv);
}

// =====================================================================
extern "C" void kernel_launch(void* const* d_in, const int* in_sizes, int n_in,
                              void* d_out, int out_size)
{
    const float* x      = (const float*)d_in[0];
    const float* cg_s   = (const float*)d_in[1];
    const float* cg_b   = (const float*)d_in[2];
    const float* pw1_w  = (const float*)d_in[3];
    const float* pw1_b  = (const float*)d_in[4];
    const float* dw_w   = (const float*)d_in[5];
    const float* dw_b   = (const float*)d_in[6];
    const float* pw2_w  = (const float*)d_in[7];
    const float* pw2_b  = (const float*)d_in[8];
    const float* beta   = (const float*)d_in[9];
    const float* at_s   = (const float*)d_in[10];
    const float* at_b   = (const float*)d_in[11];
    const float* qkv_w  = (const float*)d_in[12];
    const float* qkv_b  = (const float*)d_in[13];
    const float* rpe    = (const float*)d_in[14];
    const float* proj_w = (const float*)d_in[15];
    const float* proj_b = (const float*)d_in[16];
    const float* alpha  = (const float*)d_in[17];
    const float* ff_s   = (const float*)d_in[18];
    const float* ff_b   = (const float*)d_in[19];
    const float* fc1_w  = (const float*)d_in[20];
    const float* fc1_b  = (const float*)d_in[21];
    const float* fc2_w  = (const float*)d_in[22];
    const float* fc2_b  = (const float*)d_in[23];
    const float* gamma  = (const float*)d_in[24];
    float* out = (float*)d_out;

    bf16 *wbf, *a512, *g256, *qkvb, *aob, *x1n, *x2n;
    float *x1, *x2;
    cudaGetSymbolAddress((void**)&wbf,  g_wbf);
    cudaGetSymbolAddress((void**)&a512, g_a512);
    cudaGetSymbolAddress((void**)&g256, g_g256);
    cudaGetSymbolAddress((void**)&qkvb, g_qkv);
    cudaGetSymbolAddress((void**)&aob,  g_ao);
    cudaGetSymbolAddress((void**)&x1n,  g_x1n);
    cudaGetSymbolAddress((void**)&x2n,  g_x2n);
    cudaGetSymbolAddress((void**)&x1,   g_x1);
    cudaGetSymbolAddress((void**)&x2,   g_x2);

    cudaFuncSetAttribute(tc_gemm<1, 4, 0, false, true , 2>, cudaFuncAttributeMaxDynamicSharedMemorySize, SMB);
    cudaFuncSetAttribute(tc_gemm<1, 3, 0, false, false, 2>, cudaFuncAttributeMaxDynamicSharedMemorySize, SMB);
    cudaFuncSetAttribute(tc_gemm<2, 1, 2, true , false, 1>, cudaFuncAttributeMaxDynamicSharedMemorySize, SMB);
    cudaFuncSetAttribute(tc_gemm<1, 1, 2, true , false, 2>, cudaFuncAttributeMaxDynamicSharedMemorySize, SMB);
    cudaFuncSetAttribute(tc_gemm<1, 2, 1, false, false, 1>, cudaFuncAttributeMaxDynamicSharedMemorySize, SMB);
    cudaFuncSetAttribute(tc_gemm<2, 1, 2, false, false, 1>, cudaFuncAttributeMaxDynamicSharedMemorySize, SMB);

    const int NPB  = 1152;   // 64-px tiles
    const int NPB2 = 576;    // 128-px tiles

    // ---- prep ----
    wcvt_kernel<<<256, 256>>>(pw1_w, pw2_w, qkv_w, proj_w, fc1_w, fc2_w, wbf);

    // ---- conv gated block (RMS fused into pw1, NPX=2) ----
    tc_gemm<1, 4, 0, false, true, 2><<<NPB2, 256, SMB>>>(
        nullptr, wbf + 0, pw1_b, nullptr, nullptr, nullptr, a512, nullptr,
        cg_s, cg_b, x);
    dwgate_kernel<<<2 * 256 * 18, 256>>>(a512, dw_w, dw_b, g256);
    tc_gemm<2, 1, 2, true, false, 1><<<NPB, 256, SMB>>>(
        g256, wbf + 65536, pw2_b, x, beta, x1, nullptr, x1n, at_s, at_b, nullptr);

    // ---- window attention (qkv NPX=2, proj NPX=2) ----
    tc_gemm<1, 3, 0, false, false, 2><<<NPB2, 256, SMB>>>(
        x1n, wbf + 98304, qkv_b, nullptr, nullptr, nullptr, qkvb, nullptr,
        nullptr, nullptr, nullptr);
    attn2_kernel<<<NWTOT * 4, 64>>>(qkvb, rpe, aob);
    tc_gemm<1, 1, 2, true, false, 2><<<NPB2, 256, SMB>>>(
        aob, wbf + 147456, proj_b, x1, alpha, x2, nullptr, x2n, ff_s, ff_b, nullptr);

    // ---- gated FFN ----
    tc_gemm<1, 2, 1, false, false, 1><<<NPB, 256, SMB>>>(
        x2n, wbf + 163840, fc1_b, nullptr, nullptr, nullptr, g256, nullptr,
        nullptr, nullptr, nullptr);
    tc_gemm<2, 1, 2, false, false, 1><<<NPB, 256, SMB>>>(
        g256, wbf + 229376, fc2_b, x2, gamma, out, nullptr, nullptr,
        nullptr, nullptr, nullptr);
}